// round 9
// baseline (speedup 1.0000x reference)
#include <cuda_runtime.h>
#include <cuda_bf16.h>
#include <string.h>
#include <math.h>

// ---------------- problem constants ----------------
#define EID   30000
#define EMB   256
#define HID   512
#define SRC_T 128
#define TRG_T 50
#define B     64
#define G3    (3*HID)          // 1536

// ---------------- device state ----------------
__device__ float g_hT[2 * HID * B];                    // transposed hidden [k][b], double buffered
__device__ float g_giEnc[(size_t)SRC_T * B * G3];      // encoder gi precomputed (incl. b_ih)
__device__ float g_A[8 * B * G3];                      // gh partials
__device__ float g_Bp[5 * B * G3];                     // gi partials (decoder)
__device__ float g_C[12 * B * HID];                    // r1 partials
__device__ float g_logits[B * EID];
__device__ float g_xdec[(EMB + 1) * B];                // transposed decoder input [k][b]
__device__ float g_rate[B];
__device__ int   g_idx[B];

// ---------------- packed fp32 FMA (sm_100+) ----------------
__device__ __forceinline__ float2 ffma2(float2 a, float2 b, float2 c) {
    unsigned long long ua, ub, uc, ud;
    memcpy(&ua, &a, 8); memcpy(&ub, &b, 8); memcpy(&uc, &c, 8);
    asm("fma.rn.f32x2 %0, %1, %2, %3;" : "=l"(ud) : "l"(ua), "l"(ub), "l"(uc));
    float2 d; memcpy(&d, &ud, 8); return d;
}

__device__ __forceinline__ float sigf(float x) { return 1.f / (1.f + expf(-x)); }
__device__ __forceinline__ void acc4(float4& a, const float4 v) {
    a.x += v.x; a.y += v.y; a.z += v.z; a.w += v.w;
}

// ---------------- 64x64 micro-kernel (4 pairs x 4 cols / thread, 128 thr) ----------------
__device__ __forceinline__ void mm64_4x4(const float* __restrict__ xs,
                                         const float* __restrict__ ws,
                                         int bpg, int cg, float2 acc[4][4]) {
    #pragma unroll 4
    for (int k = 0; k < 64; k++) {
        float2 xv[4];
        #pragma unroll
        for (int i = 0; i < 4; i++)
            xv[i] = *reinterpret_cast<const float2*>(&xs[k * 66 + 2 * (bpg + 8 * i)]);
        #pragma unroll
        for (int c = 0; c < 4; c++) {
            float w = ws[(cg * 4 + c) * 65 + k];
            float2 wp = make_float2(w, w);
            #pragma unroll
            for (int i = 0; i < 4; i++) acc[i][c] = ffma2(xv[i], wp, acc[i][c]);
        }
    }
}

__device__ __forceinline__ void store_4x4(float* __restrict__ dst, int N, int n0,
                                          int bpg, int cg, float2 acc[4][4]) {
    #pragma unroll
    for (int c = 0; c < 4; c++) {
        int n = n0 + cg * 4 + c;
        if (n >= N) continue;
        #pragma unroll
        for (int i = 0; i < 4; i++) {
            int p = bpg + 8 * i;
            dst[(size_t)(2 * p) * N + n]     = acc[i][c].x;
            dst[(size_t)(2 * p + 1) * N + n] = acc[i][c].y;
        }
    }
}

// ---------------- generic batch-64 GEMM (proven R4 kernel) ----------------
#define KT 64

template<int JT, int NTH>
__launch_bounds__(NTH)
__global__ void gemm64k(const float* __restrict__ XT, const float* __restrict__ W,
                        const float* __restrict__ bias, float* __restrict__ out,
                        int N, int ldW, int K, int kChunk)
{
    __shared__ float xs[KT * 66];
    __shared__ float ws[JT * (KT + 1)];

    const int tid = threadIdx.x;
    const int n0  = blockIdx.x * JT;
    const int kb  = blockIdx.y * kChunk;
    const int ke  = min(K, kb + kChunk);
    const int bpg = tid & 7;
    const int cg  = tid >> 3;

    float2 acc[4][4];
    #pragma unroll
    for (int i = 0; i < 4; i++)
        #pragma unroll
        for (int c = 0; c < 4; c++) acc[i][c] = make_float2(0.f, 0.f);

    for (int kt = kb; kt < ke; kt += KT) {
        const int kn = min(KT, ke - kt);
        __syncthreads();
        for (int e = tid; e < kn * 64; e += NTH) {
            int k = e >> 6, b = e & 63;
            xs[k * 66 + b] = XT[(kt + k) * 64 + b];
        }
        if (kn == KT) {
            for (int e = tid; e < JT * KT; e += NTH) {
                int nl = e >> 6, k = e & 63;
                int n = n0 + nl;
                ws[nl * (KT + 1) + k] = (n < N) ? W[(size_t)n * ldW + kt + k] : 0.f;
            }
        } else {
            for (int e = tid; e < JT * kn; e += NTH) {
                int nl = e / kn, k = e - nl * kn;
                int n = n0 + nl;
                ws[nl * (KT + 1) + k] = (n < N) ? W[(size_t)n * ldW + kt + k] : 0.f;
            }
        }
        __syncthreads();

        #pragma unroll 4
        for (int k = 0; k < kn; k++) {
            float2 xv[4];
            #pragma unroll
            for (int i = 0; i < 4; i++)
                xv[i] = *reinterpret_cast<const float2*>(&xs[k * 66 + 2 * (bpg + 8 * i)]);
            #pragma unroll
            for (int c = 0; c < 4; c++) {
                float wv = ws[(cg * 4 + c) * (KT + 1) + k];
                float2 wp = make_float2(wv, wv);
                #pragma unroll
                for (int i = 0; i < 4; i++)
                    acc[i][c] = ffma2(xv[i], wp, acc[i][c]);
            }
        }
    }

    float* o = out + (size_t)blockIdx.y * 64 * N;
    #pragma unroll
    for (int c = 0; c < 4; c++) {
        int n = n0 + cg * 4 + c;
        if (n >= N) continue;
        float bv = bias ? bias[n] : 0.f;
        #pragma unroll
        for (int i = 0; i < 4; i++) {
            int p = bpg + 8 * i;
            o[(size_t)(2 * p)     * N + n] = acc[i][c].x + bv;
            o[(size_t)(2 * p + 1) * N + n] = acc[i][c].y + bv;
        }
    }
}

// ---------------- merged decoder gi+gh GEMM: grid (24, 13) ----------------
__global__ __launch_bounds__(128)
void dec_gemm_both(const float* __restrict__ xdec, const float* __restrict__ hT,
                   const float* __restrict__ W_ih, const float* __restrict__ W_hh,
                   float* __restrict__ Bp, float* __restrict__ A)
{
    __shared__ float xs[64 * 66];
    __shared__ float ws[64 * 65];
    const int tid = threadIdx.x, jn = blockIdx.x, jk = blockIdx.y;
    const int n0 = jn * 64;
    const int bpg = tid & 7, cg = tid >> 3;

    const float* XT; const float* W; int ldW, kb, kn; float* dst;
    if (jk < 5) { XT = xdec; W = W_ih; ldW = EMB + 1; kb = jk * 64;
                  kn = min(64, (EMB + 1) - kb); dst = Bp + (size_t)jk * B * G3; }
    else        { XT = hT;   W = W_hh; ldW = HID;    kb = (jk - 5) * 64;
                  kn = 64;   dst = A + (size_t)(jk - 5) * B * G3; }

    for (int e = tid; e < 4096; e += 128) {
        int k = e >> 6, b = e & 63;
        xs[k * 66 + b] = (k < kn) ? XT[(kb + k) * 64 + b] : 0.f;
    }
    for (int e = tid; e < 4096; e += 128) {
        int nl = e >> 6, k = e & 63;
        ws[nl * 65 + k] = (k < kn) ? W[(size_t)(n0 + nl) * ldW + kb + k] : 0.f;
    }
    __syncthreads();

    float2 acc[4][4];
    #pragma unroll
    for (int i = 0; i < 4; i++)
        #pragma unroll
        for (int c = 0; c < 4; c++) acc[i][c] = make_float2(0.f, 0.f);
    mm64_4x4(xs, ws, bpg, cg, acc);
    store_4x4(dst, G3, n0, bpg, cg, acc);
}

// ---------------- r1 GEMM with fused concat gather: grid (8, 12) ----------------
__global__ __launch_bounds__(128)
void r1_gemm_fused(const float* __restrict__ emb_mt, const float* __restrict__ hT,
                   const float* __restrict__ W_r1, float* __restrict__ C)
{
    __shared__ float xs[64 * 66];
    __shared__ float ws[64 * 65];
    const int tid = threadIdx.x, jn = blockIdx.x, jk = blockIdx.y;
    const int n0 = jn * 64, k0 = jk * 64;
    const int bpg = tid & 7, cg = tid >> 3;

    if (k0 < EMB) {
        for (int e = tid; e < 4096; e += 128) {
            int b = e >> 6, kl = e & 63;
            xs[kl * 66 + b] = emb_mt[(size_t)g_idx[b] * EMB + k0 + kl];
        }
    } else {
        for (int e = tid; e < 4096; e += 128) {
            int k = e >> 6, b = e & 63;
            xs[k * 66 + b] = hT[(k0 - EMB + k) * 64 + b];
        }
    }
    for (int e = tid; e < 4096; e += 128) {
        int nl = e >> 6, k = e & 63;
        ws[nl * 65 + k] = W_r1[(size_t)(n0 + nl) * (EMB + HID) + k0 + k];
    }
    __syncthreads();

    float2 acc[4][4];
    #pragma unroll
    for (int i = 0; i < 4; i++)
        #pragma unroll
        for (int c = 0; c < 4; c++) acc[i][c] = make_float2(0.f, 0.f);
    mm64_4x4(xs, ws, bpg, cg, acc);
    store_4x4(C + (size_t)jk * B * HID, HID, n0, bpg, cg, acc);
}

// ---------------- GRU gate combine, float4-vectorized (4 j per thread) ----------------
__global__ void gru_combine_v4(const float* __restrict__ Ap, int nA,
                               const float* __restrict__ Bsrc, int nB,
                               const float* __restrict__ b_ih, const float* __restrict__ b_hh,
                               const float* __restrict__ hin, float* __restrict__ hout,
                               const int* __restrict__ src_len, int t)
{
    int i = blockIdx.x * blockDim.x + threadIdx.x;     // 8192 threads
    if (i >= B * HID / 4) return;
    const int b = i >> 7;
    const int j0 = (i & 127) * 4;

    float4 ar = *(const float4*)&b_hh[j0];
    float4 az = *(const float4*)&b_hh[j0 + 512];
    float4 an = *(const float4*)&b_hh[j0 + 1024];
    #pragma unroll 4
    for (int p = 0; p < nA; p++) {
        const float* base = Ap + (size_t)(p * B + b) * G3;
        acc4(ar, *(const float4*)&base[j0]);
        acc4(az, *(const float4*)&base[j0 + 512]);
        acc4(an, *(const float4*)&base[j0 + 1024]);
    }
    float4 br, bz, bn;
    if (nB == 0) {
        const float* base = Bsrc + (size_t)b * G3;     // gi with bias included
        br = *(const float4*)&base[j0];
        bz = *(const float4*)&base[j0 + 512];
        bn = *(const float4*)&base[j0 + 1024];
    } else {
        br = *(const float4*)&b_ih[j0];
        bz = *(const float4*)&b_ih[j0 + 512];
        bn = *(const float4*)&b_ih[j0 + 1024];
        #pragma unroll 4
        for (int p = 0; p < nB; p++) {
            const float* base = Bsrc + (size_t)(p * B + b) * G3;
            acc4(br, *(const float4*)&base[j0]);
            acc4(bz, *(const float4*)&base[j0 + 512]);
            acc4(bn, *(const float4*)&base[j0 + 1024]);
        }
    }

    const bool keep = src_len ? !(t < src_len[b]) : false;
    const float* arp = (const float*)&ar; const float* azp = (const float*)&az;
    const float* anp = (const float*)&an;
    const float* brp = (const float*)&br; const float* bzp = (const float*)&bz;
    const float* bnp = (const float*)&bn;
    #pragma unroll
    for (int u = 0; u < 4; u++) {
        int j = j0 + u;
        float r = sigf(arp[u] + brp[u]);
        float z = sigf(azp[u] + bzp[u]);
        float n = tanhf(bnp[u] + r * anp[u]);
        float ho = hin[j * 64 + b];
        float hv = (1.f - z) * n + z * ho;
        hout[j * 64 + b] = keep ? ho : hv;
    }
}

// ---------------- single-pass log-softmax + first-argmax + write ----------------
__global__ void softmax_argmax(const float* __restrict__ logits, float* __restrict__ out,
                               int row, int* __restrict__ idxout)
{
    __shared__ float rm[1024], rs[1024];
    __shared__ int   ri[1024];
    const int b = blockIdx.x, tid = threadIdx.x;
    const float* L = logits + (size_t)b * EID;

    float m = -3.4e38f, sum = 0.f; int ix = 0x7fffffff;
    for (int n = tid; n < EID; n += 1024) {
        float v = L[n];
        if (v > m) { sum = sum * expf(m - v) + 1.f; m = v; ix = n; }
        else       sum += expf(v - m);
    }
    rm[tid] = m; rs[tid] = sum; ri[tid] = ix;
    __syncthreads();
    for (int st = 512; st; st >>= 1) {
        if (tid < st) {
            float m1 = rm[tid], m2 = rm[tid + st], s1 = rs[tid], s2 = rs[tid + st];
            int i1 = ri[tid], i2 = ri[tid + st];
            float M = fmaxf(m1, m2);
            rs[tid] = s1 * expf(m1 - M) + s2 * expf(m2 - M);
            rm[tid] = M;
            ri[tid] = (m2 > m1) ? i2 : ((m1 > m2) ? i1 : min(i1, i2));
        }
        __syncthreads();
    }
    float lse = rm[0] + logf(rs[0]);
    if (tid == 0) idxout[b] = ri[0];

    float* O = out + ((size_t)row * B + b) * EID;
    for (int n = tid; n < EID; n += 1024) O[n] = L[n] - lse;
}

// ---------------- rate head finish ----------------
__global__ void rate_head(const float* __restrict__ C, const float* __restrict__ b_r1,
                          const float* __restrict__ W_r2, const float* __restrict__ b_r2,
                          float* __restrict__ outRate, int row, float* __restrict__ rateState)
{
    const int b = blockIdx.x, j = threadIdx.x;   // 512 threads
    float v = b_r1[j];
    #pragma unroll
    for (int p = 0; p < 12; p++) v += C[((size_t)p * B + b) * HID + j];
    v = fmaxf(v, 0.f) * W_r2[j];
    __shared__ float sv[512];
    sv[j] = v; __syncthreads();
    for (int s = 256; s; s >>= 1) { if (j < s) sv[j] += sv[j + s]; __syncthreads(); }
    if (j == 0) {
        float pr = sigf(sv[0] + b_r2[0]);
        outRate[(size_t)row * B + b] = pr;
        rateState[b] = pr;
    }
}

// ---------------- input builders / prep ----------------
__global__ void build_xdec(const float* __restrict__ emb_dec, const int* __restrict__ idx,
                           const float* __restrict__ rate, float* __restrict__ xT)
{
    int i = blockIdx.x * 256 + threadIdx.x;
    if (i >= (EMB + 1) * 64) return;
    int k = i >> 6, b = i & 63;
    xT[i] = (k < EMB) ? emb_dec[(size_t)idx[b] * EMB + k] : rate[b];
}

__global__ void init_state(float* __restrict__ hT0, int* __restrict__ idx, float* __restrict__ rate,
                           const int* __restrict__ trg_eid, const float* __restrict__ trg_rate)
{
    int i = blockIdx.x * 256 + threadIdx.x;
    if (i < HID * B) hT0[i] = 0.f;
    if (i < B) { idx[i] = trg_eid[i]; rate[i] = trg_rate[i]; }
}

__global__ void enc_gi(const float* __restrict__ src, const float* __restrict__ W_ih,
                       const float* __restrict__ b_ih, float* __restrict__ out)
{
    int j = blockIdx.x * 256 + threadIdx.x;   // < 1536
    int tb = blockIdx.y;                       // < 128*64
    const float* x = src + (size_t)tb * 3;
    out[(size_t)tb * G3 + j] = b_ih[j] + x[0] * W_ih[j * 3] + x[1] * W_ih[j * 3 + 1]
                                       + x[2] * W_ih[j * 3 + 2];
}

// ---------------- host launcher ----------------
extern "C" void kernel_launch(void* const* d_in, const int* in_sizes, int n_in,
                              void* d_out, int out_size)
{
    const float* src      = (const float*)d_in[0];
    const int*   src_len  = (const int*)  d_in[1];
    const int*   trg_eid  = (const int*)  d_in[2];
    const float* trg_rate = (const float*)d_in[3];
    const float* W_ih_enc = (const float*)d_in[4];
    const float* W_hh_enc = (const float*)d_in[5];
    const float* b_ih_enc = (const float*)d_in[6];
    const float* b_hh_enc = (const float*)d_in[7];
    const float* emb_dec  = (const float*)d_in[8];
    const float* W_ih_dec = (const float*)d_in[9];
    const float* W_hh_dec = (const float*)d_in[10];
    const float* b_ih_dec = (const float*)d_in[11];
    const float* b_hh_dec = (const float*)d_in[12];
    const float* emb_mt   = (const float*)d_in[13];
    const float* W_eid    = (const float*)d_in[14];
    const float* b_eid    = (const float*)d_in[15];
    const float* W_r1     = (const float*)d_in[16];
    const float* b_r1     = (const float*)d_in[17];
    const float* W_r2     = (const float*)d_in[18];
    const float* b_r2     = (const float*)d_in[19];
    float* out = (float*)d_out;
    float* out_rate = out + (size_t)TRG_T * B * EID;

    float *hT, *giEnc, *A, *Bp, *C, *logits, *xdec, *rate;
    int* idx;
    cudaGetSymbolAddress((void**)&hT,     g_hT);
    cudaGetSymbolAddress((void**)&giEnc,  g_giEnc);
    cudaGetSymbolAddress((void**)&A,      g_A);
    cudaGetSymbolAddress((void**)&Bp,     g_Bp);
    cudaGetSymbolAddress((void**)&C,      g_C);
    cudaGetSymbolAddress((void**)&logits, g_logits);
    cudaGetSymbolAddress((void**)&xdec,   g_xdec);
    cudaGetSymbolAddress((void**)&rate,   g_rate);
    cudaGetSymbolAddress((void**)&idx,    g_idx);
    float* hbuf[2] = { hT, hT + HID * B };

    // zero output row 0 (eid + rate)
    cudaMemsetAsync(out, 0, (size_t)B * EID * sizeof(float), 0);
    cudaMemsetAsync(out_rate, 0, B * sizeof(float), 0);

    init_state<<<128, 256>>>(hbuf[0], idx, rate, trg_eid, trg_rate);
    enc_gi<<<dim3(6, SRC_T * B), 256>>>(src, W_ih_enc, b_ih_enc, giEnc);

    // ---------- encoder: 128 masked GRU steps (2 nodes/step) ----------
    for (int t = 0; t < SRC_T; t++) {
        gemm64k<64, 128><<<dim3(24, 8), 128>>>(hbuf[t & 1], W_hh_enc, nullptr, A,
                                               G3, HID, HID, 64);
        gru_combine_v4<<<32, 256>>>(A, 8, giEnc + (size_t)t * B * G3, 0,
                                    nullptr, b_hh_enc, hbuf[t & 1], hbuf[(t + 1) & 1],
                                    src_len, t);
    }

    // ---------- decoder: 49 autoregressive steps (7 nodes/step) ----------
    for (int s = 0; s < TRG_T - 1; s++) {
        const int pi = s & 1, po = (s + 1) & 1;
        build_xdec<<<65, 256>>>(emb_dec, idx, rate, xdec);
        dec_gemm_both<<<dim3(24, 13), 128>>>(xdec, hbuf[pi], W_ih_dec, W_hh_dec, Bp, A);
        gru_combine_v4<<<32, 256>>>(A, 8, Bp, 5, b_ih_dec, b_hh_dec,
                                    hbuf[pi], hbuf[po], nullptr, 0);
        // big output projection: one wave of 469 co-resident blocks
        gemm64k<64, 128><<<dim3(469, 1), 128>>>(hbuf[po], W_eid, b_eid, logits,
                                                EID, HID, HID, HID);
        softmax_argmax<<<64, 1024>>>(logits, out, s + 1, idx);
        r1_gemm_fused<<<dim3(8, 12), 128>>>(emb_mt, hbuf[po], W_r1, C);
        rate_head<<<64, 512>>>(C, b_r1, W_r2, b_r2, out_rate, s + 1, rate);
    }
}